// round 11
// baseline (speedup 1.0000x reference)
#include <cuda_runtime.h>
#include <cuda_fp16.h>
#include <cstdint>

// Correlation layer via band-restricted mma.sync (m16n8k16 fp16, fp32 accum).
// out[b, di*9+dj, h, w] = sum_c f1[b,c,h,w] * f2[b,c,h+di-4,w+dj-4]
// B=8, C=256, H=64, W=128, D=81.
//
// R11: f1 never touches smem: A-fragments come from 8 direct LDG.32 per
//      thread per chunk (register prefetch, one chunk ahead, in-reg
//      cvt+pack to fp16). smem holds only f2 (padded fp16 gmem pre-cast,
//      all-16B division-free cp.async), NBUF=4. CTA per (h, b, di-half),
//      2 CTAs/SM co-resident.

#define NB 8
#define NC 256
#define NH 64
#define NW 128
#define ND 81
#define PW 136                       // padded f2 row (halves); data at cols [4,132)
#define CNW (NH * NW)                // f1 channel stride in words

#define RSTRIDE 272                  // f2 c-row bytes in smem; %128==16 -> LDSM conflict-free
#define F2ROW (16 * RSTRIDE)         // 4352 B per r per 16-c chunk
#define BUFSZ (5 * F2ROW)            // 21760 (worst-case RN=5, uniform for both halves)
#define NBUF 4
#define SMEM_SZ (NBUF * BUFSZ)       // 87040 B -> 2 CTAs/SM
#define STAGE_W 25

__device__ __half g_f2h[(size_t)NB * NC * NH * PW];

// ---------------- fp32 -> padded fp16 cast for f2 ----------------
__global__ void cast_kernel(const float* __restrict__ f2) {
    int idx = blockIdx.x * 256 + threadIdx.x;   // one 16B output seg
    int row = idx / 17, sg = idx % 17;          // row = ((b*NC+c)*NH+h)
    const float* src = f2 + (size_t)row * NW;
    __half hv[8];
    #pragma unroll
    for (int k = 0; k < 8; k++) {
        int col = 8 * sg - 4 + k;
        float v = (col >= 0 && col < NW) ? src[col] : 0.0f;
        hv[k] = __float2half_rn(v);
    }
    *reinterpret_cast<uint4*>(g_f2h + (size_t)row * PW + 8 * sg) =
        *reinterpret_cast<const uint4*>(hv);
}

// ---------------- PTX helpers ----------------
__device__ __forceinline__ void cpa16(uint32_t dst, const void* src) {
    asm volatile("cp.async.ca.shared.global [%0], [%1], 16;" :: "r"(dst), "l"(src));
}
__device__ __forceinline__ void ldsm4t(uint32_t& r0, uint32_t& r1,
                                       uint32_t& r2, uint32_t& r3, uint32_t a) {
    asm volatile("ldmatrix.sync.aligned.m8n8.x4.trans.shared.b16 {%0,%1,%2,%3}, [%4];"
                 : "=r"(r0), "=r"(r1), "=r"(r2), "=r"(r3) : "r"(a));
}
__device__ __forceinline__ void ldsm2t(uint32_t& r0, uint32_t& r1, uint32_t a) {
    asm volatile("ldmatrix.sync.aligned.m8n8.x2.trans.shared.b16 {%0,%1}, [%2];"
                 : "=r"(r0), "=r"(r1) : "r"(a));
}
__device__ __forceinline__ void mma16816(float* d, uint32_t a0, uint32_t a1,
                                         uint32_t a2, uint32_t a3,
                                         uint32_t b0, uint32_t b1) {
    asm volatile("mma.sync.aligned.m16n8k16.row.col.f32.f16.f16.f32 "
                 "{%0,%1,%2,%3}, {%4,%5,%6,%7}, {%8,%9}, {%0,%1,%2,%3};"
                 : "+f"(d[0]), "+f"(d[1]), "+f"(d[2]), "+f"(d[3])
                 : "r"(a0), "r"(a1), "r"(a2), "r"(a3), "r"(b0), "r"(b1));
}
__device__ __forceinline__ uint32_t pkh2(float lo, float hi) {
    __half2 h = __floats2half2_rn(lo, hi);
    return *reinterpret_cast<uint32_t*>(&h);
}

// ---------------- main kernel ----------------
__global__ void __launch_bounds__(256, 2)
corr_mma(const float* __restrict__ f1, float* __restrict__ out) {
    extern __shared__ char smem[];
    const uint32_t sb = (uint32_t)__cvta_generic_to_shared(smem);
    const int tid = threadIdx.x;
    const int lane = tid & 31, m = tid >> 5;    // warp = m16 w-block
    const int h = blockIdx.x, b = blockIdx.y, half = blockIdx.z;

    const int R0 = half ? 4 : 0;
    const int RN = half ? 5 : 4;

    float acc[5][3][4];
    #pragma unroll
    for (int ri = 0; ri < 5; ri++)
        #pragma unroll
        for (int t = 0; t < 3; t++)
            #pragma unroll
            for (int k = 0; k < 4; k++)
                acc[ri][t][k] = 0.0f;

    // f1 register-direct A source: thread needs (c, w) for
    // c in {2tig, 2tig+1, 2tig+8, 2tig+9}, w in {16m+gid, 16m+gid+8}.
    const int gid = lane >> 2, tig = lane & 3;
    const float* f1p = f1 + ((size_t)b * NC + 2 * tig) * CNW + h * NW + 16 * m + gid;
    // B ldsm addresses: x4 -> tiles at padded cols (16m, 16m+8); x2 -> 16m+16.
    const uint32_t b4_off = (uint32_t)(lane & 15) * RSTRIDE + ((lane >> 4) << 4) + 32 * m;
    const uint32_t b2_off = (uint32_t)(lane & 15) * RSTRIDE + 32 * m + 32;

    // Division-free f2 loader: thread (ci, sg) copies seg sg of each r's row;
    // sg==0 threads also copy the 17th seg.
    const int ci = tid >> 4, sg = tid & 15;
    auto issue = [&](int cc) {
        const int c0 = cc * 16;
        const uint32_t dbase = sb + (cc & (NBUF - 1)) * BUFSZ;
        #pragma unroll
        for (int r = 0; r < 5; r++) {
            if (r < RN) {
                int gr = h + R0 + r - 4;
                gr = gr < 0 ? 0 : (gr > NH - 1 ? NH - 1 : gr);  // clamp; invalid di never stored
                const __half* rowp = g_f2h + ((size_t)(b * NC + c0 + ci) * NH + gr) * PW;
                const uint32_t d = dbase + r * F2ROW + ci * RSTRIDE;
                cpa16(d + 16 * sg, rowp + 8 * sg);
                if (sg == 0) cpa16(d + 256, rowp + 128);
            }
        }
    };

    // f1 prefetch for one chunk: 8 scattered LDG.32 at immediate offsets.
    float av[8];
    auto ldf1 = [&](int cc) {
        const float* p = f1p + (size_t)cc * 16 * CNW;
        av[0] = __ldg(p);                 av[1] = __ldg(p + 8);
        av[2] = __ldg(p + CNW);           av[3] = __ldg(p + CNW + 8);
        av[4] = __ldg(p + 8 * CNW);       av[5] = __ldg(p + 8 * CNW + 8);
        av[6] = __ldg(p + 9 * CNW);       av[7] = __ldg(p + 9 * CNW + 8);
    };

    issue(0); asm volatile("cp.async.commit_group;");
    issue(1); asm volatile("cp.async.commit_group;");
    issue(2); asm volatile("cp.async.commit_group;");
    ldf1(0);

    for (int cc = 0; cc < 16; cc++) {
        asm volatile("cp.async.wait_group 2;");   // f2 chunk cc complete
        __syncthreads();
        if (cc + 3 < 16) issue(cc + 3);           // buf (cc+3)&3 == (cc-1)&3: consumed before barrier
        asm volatile("cp.async.commit_group;");   // empty at tail keeps count uniform

        // Pack this chunk's A fragments, then immediately prefetch next chunk.
        uint32_t a0 = pkh2(av[0], av[2]);
        uint32_t a1 = pkh2(av[1], av[3]);
        uint32_t a2 = pkh2(av[4], av[6]);
        uint32_t a3 = pkh2(av[5], av[7]);
        if (cc + 1 < 16) ldf1(cc + 1);            // latency hides behind LDSM+MMA below

        const uint32_t cbase = sb + (cc & (NBUF - 1)) * BUFSZ;
        #pragma unroll
        for (int ri = 0; ri < 5; ri++) {
            if (ri < RN) {
                const uint32_t rb = cbase + ri * F2ROW;
                uint32_t q0, q1, q2, q3, e0, e1;
                ldsm4t(q0, q1, q2, q3, rb + b4_off);
                ldsm2t(e0, e1, rb + b2_off);
                mma16816(acc[ri][0], a0, a1, a2, a3, q0, q1);
                mma16816(acc[ri][1], a0, a1, a2, a3, q2, q3);
                mma16816(acc[ri][2], a0, a1, a2, a3, e0, e1);
            }
        }
    }

    // ---------------- epilogue: band extraction via per-warp staging ----------------
    __syncthreads();   // buffers dead; staging aliases them
    float* stage = reinterpret_cast<float*>(smem) + m * 16 * STAGE_W;
    const int l16 = lane & 15, dh = lane >> 4;
    #pragma unroll
    for (int ri = 0; ri < 5; ri++) {
        if (ri < RN) {
            const int r = R0 + ri;
            #pragma unroll
            for (int t = 0; t < 3; t++) {
                stage[gid * STAGE_W + 8 * t + 2 * tig]           = acc[ri][t][0];
                stage[gid * STAGE_W + 8 * t + 2 * tig + 1]       = acc[ri][t][1];
                stage[(gid + 8) * STAGE_W + 8 * t + 2 * tig]     = acc[ri][t][2];
                stage[(gid + 8) * STAGE_W + 8 * t + 2 * tig + 1] = acc[ri][t][3];
            }
            __syncwarp();
            const int gr = h + r - 4;
            const bool valid = (gr >= 0 && gr < NH);
            // out[b, r*9+dj, h, 16m+l16] = band[l16][l16+dj] (padded-col space)
            #pragma unroll
            for (int rd = 0; rd < 5; rd++) {
                int dj = 2 * rd + dh;
                if (dj < 9) {
                    float v = valid ? stage[l16 * STAGE_W + l16 + dj] : 0.0f;
                    out[(((size_t)b * ND + r * 9 + dj) * NH + h) * NW + 16 * m + l16] = v;
                }
            }
            __syncwarp();
        }
    }
}

extern "C" void kernel_launch(void* const* d_in, const int* in_sizes, int n_in,
                              void* d_out, int out_size) {
    const float* f1 = (const float*)d_in[0];
    const float* f2 = (const float*)d_in[1];
    float* out = (float*)d_out;

    cudaFuncSetAttribute(corr_mma, cudaFuncAttributeMaxDynamicSharedMemorySize, SMEM_SZ);

    // (NB*NC*NH rows) * 17 segs / 256 threads = 8704 blocks exactly
    cast_kernel<<<8704, 256>>>(f2);
    corr_mma<<<dim3(NH, NB, 2), 256, SMEM_SZ>>>(f1, out);
}